// round 3
// baseline (speedup 1.0000x reference)
#include <cuda_runtime.h>

#define B_   4096
#define T_   200
#define S_   20
#define NF_  16
#define NT_  2
#define H1_  128
#define H2_  64
#define H3_  32
#define G1_  512   // 4*H1
#define G2_  256   // 4*H2
#define K1_  144   // NF + H1
#define K2_  192   // H1 + H2
#define BT_  32
#define NBLK (B_ / BT_)     // 128
#define NTHREADS 512

// ---------------- device scratch (prepped weights) ----------------
__device__ float d_WcT1[K1_ * G1_];   // [k][g], k<16: Wih1 col, else Whh1 col
__device__ float d_WcT2[K2_ * G2_];   // [k][g], k<128: Wih2 col, else Whh2 col
__device__ float d_b1[G1_];
__device__ float d_b2[G2_];

// ---------------- shared memory layout (floats) ----------------
// Input rows padded to 36 floats (144B) so every row start is 16B-aligned
// and u64-pair (ulonglong2 / LDS.128) loads are legal.
#define IN1_ROW 36
#define IN1_ROWU 18                             // u64 per row
#define IN1_OFF 0                               // [K1_][36]
#define IN2_OFF (K1_ * IN1_ROW)                 // 5184   [H2_][36]
#define G1S_ROW 516
#define G1S_OFF (IN2_OFF + H2_ * IN1_ROW)       // 7488   [BT_][516]
#define G2S_ROW 260
#define G2S_OFF (G1S_OFF + BT_ * G1S_ROW)       // 24000  [BT_][260]
#define C1_OFF  (G2S_OFF + BT_ * G2S_ROW)       // 32320  [H1_][33]
#define C2_OFF  (C1_OFF + H1_ * 33)             // 36544  [H2_][33]
#define DS_OFF  (C2_OFF + H2_ * 33)             // 38656  [BT_][33]
#define SMEM_FLOATS (DS_OFF + H3_ * 33)         // 39712
#define SMEM_BYTES  (SMEM_FLOATS * 4)           // 158848

// ---------------- f32x2 helpers ----------------
typedef unsigned long long u64;

__device__ __forceinline__ u64 pack2(float lo, float hi) {
    u64 r;
    asm("mov.b64 %0, {%1, %2};" : "=l"(r) : "f"(lo), "f"(hi));
    return r;
}
__device__ __forceinline__ void unpack2(u64 v, float& lo, float& hi) {
    asm("mov.b64 {%0, %1}, %2;" : "=f"(lo), "=f"(hi) : "l"(v));
}
__device__ __forceinline__ u64 fma2(u64 a, u64 b, u64 c) {
    u64 d;
    asm("fma.rn.f32x2 %0, %1, %2, %3;" : "=l"(d) : "l"(a), "l"(b), "l"(c));
    return d;
}

__device__ __forceinline__ float tanhf_(float x) {
    float y;
    asm("tanh.approx.f32 %0, %1;" : "=f"(y) : "f"(x));
    return y;
}
// sigmoid(x) = 0.5*tanh(0.5x) + 0.5 : 1 MUFU + 2 FMA instead of EX2+RCP+add
__device__ __forceinline__ float sigmoidf_(float x) {
    return fmaf(0.5f, tanhf_(0.5f * x), 0.5f);
}

// ---------------- one recurrent step (both LSTM layers) ----------------
__device__ __forceinline__ void lstm_step(float* sm, int tid) {
    const u64* in1u = (const u64*)(sm + IN1_OFF);
    const u64* in2u = (const u64*)(sm + IN2_OFF);

    // ---- GEMM1: g1[bt][g] = b1[g] + sum_k in1[k][bt] * WcT1[k][g] ----
    {
        const int s  = tid & 255;   // gate pair: gates 2s, 2s+1
        const int bs = tid >> 8;    // 0/1 -> pairs bs*8 .. bs*8+7
        u64 acc0[8], acc1[8];
        {
            float bb0 = d_b1[2 * s], bb1 = d_b1[2 * s + 1];
            u64 p0 = pack2(bb0, bb0), p1 = pack2(bb1, bb1);
#pragma unroll
            for (int j = 0; j < 8; j++) { acc0[j] = p0; acc1[j] = p1; }
        }
        const float2* __restrict__ w = (const float2*)d_WcT1 + s;  // + k*256
        const u64* hrow = in1u + bs * 8;
#pragma unroll 4
        for (int k = 0; k < K1_; k++) {
            float2 wv = w[k * (G1_ / 2)];
            u64 wa = pack2(wv.x, wv.x);
            u64 wb = pack2(wv.y, wv.y);
            const ulonglong2* h = (const ulonglong2*)(hrow + k * IN1_ROWU);
            ulonglong2 h01 = h[0];
            ulonglong2 h23 = h[1];
            ulonglong2 h45 = h[2];
            ulonglong2 h67 = h[3];
            acc0[0] = fma2(wa, h01.x, acc0[0]); acc1[0] = fma2(wb, h01.x, acc1[0]);
            acc0[1] = fma2(wa, h01.y, acc0[1]); acc1[1] = fma2(wb, h01.y, acc1[1]);
            acc0[2] = fma2(wa, h23.x, acc0[2]); acc1[2] = fma2(wb, h23.x, acc1[2]);
            acc0[3] = fma2(wa, h23.y, acc0[3]); acc1[3] = fma2(wb, h23.y, acc1[3]);
            acc0[4] = fma2(wa, h45.x, acc0[4]); acc1[4] = fma2(wb, h45.x, acc1[4]);
            acc0[5] = fma2(wa, h45.y, acc0[5]); acc1[5] = fma2(wb, h45.y, acc1[5]);
            acc0[6] = fma2(wa, h67.x, acc0[6]); acc1[6] = fma2(wb, h67.x, acc1[6]);
            acc0[7] = fma2(wa, h67.y, acc0[7]); acc1[7] = fma2(wb, h67.y, acc1[7]);
        }
#pragma unroll
        for (int j = 0; j < 8; j++) {
            int p = bs * 8 + j;
            float a0, a1, c0, c1;
            unpack2(acc0[j], a0, a1);   // gate 2s   : bt 2p, 2p+1
            unpack2(acc1[j], c0, c1);   // gate 2s+1 : bt 2p, 2p+1
            *(float2*)(sm + G1S_OFF + (2 * p) * G1S_ROW + 2 * s)     = make_float2(a0, c0);
            *(float2*)(sm + G1S_OFF + (2 * p + 1) * G1S_ROW + 2 * s) = make_float2(a1, c1);
        }
    }
    __syncthreads();

    // ---- pointwise LSTM1 -> h1 into in1 rows 16.., c1 ----
    {
        const int uu = tid & 127;
        const int q  = tid >> 7;     // 0..3 -> bt = 8q..8q+7
#pragma unroll
        for (int j2 = 0; j2 < 4; j2++) {
            float hp[2];
#pragma unroll
            for (int half = 0; half < 2; half++) {
                int bt = 8 * q + 2 * j2 + half;
                const float* row = sm + G1S_OFF + bt * G1S_ROW;
                float gi = row[uu], gf = row[H1_ + uu], gg = row[2 * H1_ + uu], go = row[3 * H1_ + uu];
                float c  = sm[C1_OFF + uu * 33 + bt];
                float cn = sigmoidf_(gf) * c + sigmoidf_(gi) * tanhf_(gg);
                float hn = sigmoidf_(go) * tanhf_(cn);
                sm[C1_OFF + uu * 33 + bt] = cn;
                hp[half] = hn;
            }
            *(float2*)(sm + IN1_OFF + (NF_ + uu) * IN1_ROW + 2 * (4 * q + j2)) = make_float2(hp[0], hp[1]);
        }
    }
    __syncthreads();

    // ---- GEMM2: g2[bt][g] = b2[g] + sum h1*Wih2 + sum h2*Whh2 ----
    {
        const int s2  = tid & 127;   // gates 2s2, 2s2+1
        const int bs2 = tid >> 7;    // 0..3 -> pairs bs2*4 .. +3
        u64 acc0[4], acc1[4];
        {
            float bb0 = d_b2[2 * s2], bb1 = d_b2[2 * s2 + 1];
            u64 p0 = pack2(bb0, bb0), p1 = pack2(bb1, bb1);
#pragma unroll
            for (int j = 0; j < 4; j++) { acc0[j] = p0; acc1[j] = p1; }
        }
        const float2* __restrict__ w = (const float2*)d_WcT2 + s2;  // + k*128
        const u64* h1row = in1u + NF_ * IN1_ROWU + bs2 * 4;
#pragma unroll 4
        for (int k = 0; k < H1_; k++) {
            float2 wv = w[k * (G2_ / 2)];
            u64 wa = pack2(wv.x, wv.x);
            u64 wb = pack2(wv.y, wv.y);
            const ulonglong2* h = (const ulonglong2*)(h1row + k * IN1_ROWU);
            ulonglong2 h01 = h[0];
            ulonglong2 h23 = h[1];
            acc0[0] = fma2(wa, h01.x, acc0[0]); acc1[0] = fma2(wb, h01.x, acc1[0]);
            acc0[1] = fma2(wa, h01.y, acc0[1]); acc1[1] = fma2(wb, h01.y, acc1[1]);
            acc0[2] = fma2(wa, h23.x, acc0[2]); acc1[2] = fma2(wb, h23.x, acc1[2]);
            acc0[3] = fma2(wa, h23.y, acc0[3]); acc1[3] = fma2(wb, h23.y, acc1[3]);
        }
        const u64* h2row = in2u + bs2 * 4;
#pragma unroll 4
        for (int k = 0; k < H2_; k++) {
            float2 wv = w[(H1_ + k) * (G2_ / 2)];
            u64 wa = pack2(wv.x, wv.x);
            u64 wb = pack2(wv.y, wv.y);
            const ulonglong2* h = (const ulonglong2*)(h2row + k * IN1_ROWU);
            ulonglong2 h01 = h[0];
            ulonglong2 h23 = h[1];
            acc0[0] = fma2(wa, h01.x, acc0[0]); acc1[0] = fma2(wb, h01.x, acc1[0]);
            acc0[1] = fma2(wa, h01.y, acc0[1]); acc1[1] = fma2(wb, h01.y, acc1[1]);
            acc0[2] = fma2(wa, h23.x, acc0[2]); acc1[2] = fma2(wb, h23.x, acc1[2]);
            acc0[3] = fma2(wa, h23.y, acc0[3]); acc1[3] = fma2(wb, h23.y, acc1[3]);
        }
#pragma unroll
        for (int j = 0; j < 4; j++) {
            int p = bs2 * 4 + j;
            float a0, a1, c0, c1;
            unpack2(acc0[j], a0, a1);
            unpack2(acc1[j], c0, c1);
            *(float2*)(sm + G2S_OFF + (2 * p) * G2S_ROW + 2 * s2)     = make_float2(a0, c0);
            *(float2*)(sm + G2S_OFF + (2 * p + 1) * G2S_ROW + 2 * s2) = make_float2(a1, c1);
        }
    }
    __syncthreads();

    // ---- pointwise LSTM2 -> h2 into in2, c2 ----
    {
        const int uu = tid & 63;
        const int q  = tid >> 6;     // 0..7 -> bt = 4q..4q+3
#pragma unroll
        for (int j = 0; j < 2; j++) {
            float hp[2];
#pragma unroll
            for (int half = 0; half < 2; half++) {
                int bt = 4 * q + 2 * j + half;
                const float* row = sm + G2S_OFF + bt * G2S_ROW;
                float gi = row[uu], gf = row[H2_ + uu], gg = row[2 * H2_ + uu], go = row[3 * H2_ + uu];
                float c  = sm[C2_OFF + uu * 33 + bt];
                float cn = sigmoidf_(gf) * c + sigmoidf_(gi) * tanhf_(gg);
                float hn = sigmoidf_(go) * tanhf_(cn);
                sm[C2_OFF + uu * 33 + bt] = cn;
                hp[half] = hn;
            }
            *(float2*)(sm + IN2_OFF + uu * IN1_ROW + 2 * (2 * q + j)) = make_float2(hp[0], hp[1]);
        }
    }
    __syncthreads();
}

// ---------------- weight prep: transpose + bias fuse ----------------
__global__ void prep_kernel(const float* __restrict__ Wih1, const float* __restrict__ Whh1,
                            const float* __restrict__ bih1, const float* __restrict__ bhh1,
                            const float* __restrict__ Wih2, const float* __restrict__ Whh2,
                            const float* __restrict__ bih2, const float* __restrict__ bhh2) {
    int idx = blockIdx.x * blockDim.x + threadIdx.x;
    int stride = gridDim.x * blockDim.x;
    for (int i = idx; i < K1_ * G1_; i += stride) {
        int k = i / G1_, g = i % G1_;
        d_WcT1[i] = (k < NF_) ? Wih1[g * NF_ + k] : Whh1[g * H1_ + (k - NF_)];
    }
    for (int i = idx; i < K2_ * G2_; i += stride) {
        int k = i / G2_, g = i % G2_;
        d_WcT2[i] = (k < H1_) ? Wih2[g * H1_ + k] : Whh2[g * H2_ + (k - H1_)];
    }
    if (idx < G1_) d_b1[idx] = bih1[idx] + bhh1[idx];
    if (idx < G2_) d_b2[idx] = bih2[idx] + bhh2[idx];
}

// ---------------- main persistent kernel ----------------
__global__ void __launch_bounds__(NTHREADS, 1) lstm_main(
    const float* __restrict__ xh, const float* __restrict__ xfut,
    const float* __restrict__ Wd, const float* __restrict__ bd,
    const float* __restrict__ Wf, const float* __restrict__ bf,
    const float* __restrict__ ob, float* __restrict__ out) {
    extern __shared__ float sm[];
    const int tid = threadIdx.x;
    const int b0  = blockIdx.x * BT_;

    // zero all state (h rows, c, buffers)
    for (int i = tid; i < SMEM_FLOATS; i += NTHREADS) sm[i] = 0.0f;
    __syncthreads();

    // ---------- encoder ----------
    for (int t = 0; t < T_; t++) {
        {
            int f = tid >> 5, bt = tid & 31;
            sm[IN1_OFF + f * IN1_ROW + bt] =
                xh[(size_t)(b0 + bt) * T_ * NF_ + t * NF_ + f];
        }
        __syncthreads();
        lstm_step(sm, tid);
    }

    // cur = x_history[:, T-1, NF-NT:]
    if (tid < BT_ * NT_) {
        int bt = tid >> 1, tt = tid & 1;
        sm[IN1_OFF + (NF_ - NT_ + tt) * IN1_ROW + bt] =
            xh[(size_t)(b0 + bt) * T_ * NF_ + (T_ - 1) * NF_ + (NF_ - NT_) + tt];
    }

    // ---------- decoder ----------
    for (int st = 0; st < S_; st++) {
        if (tid < BT_ * (NF_ - NT_)) {             // 448 threads load refs
            int f = tid % (NF_ - NT_), bt = tid / (NF_ - NT_);
            sm[IN1_OFF + f * IN1_ROW + bt] =
                xfut[(size_t)(b0 + bt) * S_ * (NF_ - NT_) + st * (NF_ - NT_) + f];
        }
        __syncthreads();
        lstm_step(sm, tid);

        // dense: d = relu(h2 @ Wd^T + bd), 32x32
        {
            int du = tid & 31, bq = tid >> 5;      // bq 0..15 -> bt = bq, bq+16
            float acc0 = 0.0f, acc1 = 0.0f;
#pragma unroll 4
            for (int k = 0; k < H2_; k++) {
                float wv = Wd[du * H2_ + k];
                acc0 = fmaf(wv, sm[IN2_OFF + k * IN1_ROW + bq], acc0);
                acc1 = fmaf(wv, sm[IN2_OFF + k * IN1_ROW + bq + 16], acc1);
            }
            float bdv = bd[du];
            sm[DS_OFF + bq * 33 + du]        = fmaxf(acc0 + bdv, 0.0f);
            sm[DS_OFF + (bq + 16) * 33 + du] = fmaxf(acc1 + bdv, 0.0f);
        }
        __syncthreads();

        // pred = d @ Wf^T + bf + out_bias; write out + feedback cur
        if (tid < BT_ * NT_) {
            int bt = tid >> 1, tt = tid & 1;
            float acc = 0.0f;
#pragma unroll
            for (int k = 0; k < H3_; k++)
                acc = fmaf(sm[DS_OFF + bt * 33 + k], Wf[tt * H3_ + k], acc);
            float p = acc + bf[tt] + ob[tt];
            out[(size_t)(b0 + bt) * S_ * NT_ + st * NT_ + tt] = p;
            sm[IN1_OFF + (NF_ - NT_ + tt) * IN1_ROW + bt] = p;
        }
        __syncthreads();
    }
}

// ---------------- launch ----------------
extern "C" void kernel_launch(void* const* d_in, const int* in_sizes, int n_in,
                              void* d_out, int out_size) {
    (void)in_sizes; (void)n_in; (void)out_size;
    const float* xh   = (const float*)d_in[0];
    const float* xfut = (const float*)d_in[1];
    const float* Wih1 = (const float*)d_in[2];
    const float* Whh1 = (const float*)d_in[3];
    const float* bih1 = (const float*)d_in[4];
    const float* bhh1 = (const float*)d_in[5];
    const float* Wih2 = (const float*)d_in[6];
    const float* Whh2 = (const float*)d_in[7];
    const float* bih2 = (const float*)d_in[8];
    const float* bhh2 = (const float*)d_in[9];
    const float* Wd   = (const float*)d_in[10];
    const float* bd   = (const float*)d_in[11];
    const float* Wf   = (const float*)d_in[12];
    const float* bf   = (const float*)d_in[13];
    const float* ob   = (const float*)d_in[14];
    float* out = (float*)d_out;

    cudaFuncSetAttribute(lstm_main, cudaFuncAttributeMaxDynamicSharedMemorySize, SMEM_BYTES);
    prep_kernel<<<128, 256>>>(Wih1, Whh1, bih1, bhh1, Wih2, Whh2, bih2, bhh2);
    lstm_main<<<NBLK, NTHREADS, SMEM_BYTES>>>(xh, xfut, Wd, bd, Wf, bf, ob, out);
}

// round 4
// speedup vs baseline: 1.0489x; 1.0489x over previous
#include <cuda_runtime.h>

#define B_   4096
#define T_   200
#define S_   20
#define NF_  16
#define NT_  2
#define H1_  128
#define H2_  64
#define H3_  32
#define G1_  512   // 4*H1
#define G2_  256   // 4*H2
#define K1_  144   // NF + H1
#define K2_  192   // H1 + H2
#define BT_  32
#define NBLK (B_ / BT_)     // 128
#define NTHREADS 512

// ---------------- device scratch (prepped weights) ----------------
__device__ float d_WcT1[K1_ * G1_];   // [k][g], k<16: Wih1 col, else Whh1 col
__device__ float d_WcT2[K2_ * G2_];   // [k][g], k<128: Wih2 col, else Whh2 col
__device__ float d_b1[G1_];
__device__ float d_b2[G2_];

// ---------------- shared memory layout (floats) ----------------
// Input rows padded to 36 floats (144B) so every row start is 16B-aligned
// and u64-pair (ulonglong2 / LDS.128) loads are legal.
#define IN1_ROW 36
#define IN1_ROWU 18                             // u64 per row
#define IN1_OFF 0                               // [K1_][36]
#define IN2_OFF (K1_ * IN1_ROW)                 // 5184   [H2_][36]
#define G1S_ROW 516
#define G1S_OFF (IN2_OFF + H2_ * IN1_ROW)       // 7488   [BT_][516]
#define G2S_ROW 260
#define G2S_OFF (G1S_OFF + BT_ * G1S_ROW)       // 24000  [BT_][260]
#define C1_OFF  (G2S_OFF + BT_ * G2S_ROW)       // 32320  [H1_][33]
#define C2_OFF  (C1_OFF + H1_ * 33)             // 36544  [H2_][33]
#define DS_OFF  (C2_OFF + H2_ * 33)             // 38656  [BT_][33]
#define SMEM_FLOATS (DS_OFF + H3_ * 33)         // 39712
#define SMEM_BYTES  (SMEM_FLOATS * 4)           // 158848

// ---------------- f32x2 helpers ----------------
typedef unsigned long long u64;

__device__ __forceinline__ u64 pack2(float lo, float hi) {
    u64 r;
    asm("mov.b64 %0, {%1, %2};" : "=l"(r) : "f"(lo), "f"(hi));
    return r;
}
__device__ __forceinline__ void unpack2(u64 v, float& lo, float& hi) {
    asm("mov.b64 {%0, %1}, %2;" : "=f"(lo), "=f"(hi) : "l"(v));
}
__device__ __forceinline__ u64 fma2(u64 a, u64 b, u64 c) {
    u64 d;
    asm("fma.rn.f32x2 %0, %1, %2, %3;" : "=l"(d) : "l"(a), "l"(b), "l"(c));
    return d;
}

__device__ __forceinline__ float tanhf_(float x) {
    float y;
    asm("tanh.approx.f32 %0, %1;" : "=f"(y) : "f"(x));
    return y;
}
// sigmoid(x) = 0.5*tanh(0.5x) + 0.5 : 1 MUFU + 2 FMA instead of EX2+RCP+add
__device__ __forceinline__ float sigmoidf_(float x) {
    return fmaf(0.5f, tanhf_(0.5f * x), 0.5f);
}

// ---------------- one recurrent step (both LSTM layers) ----------------
__device__ __forceinline__ void lstm_step(float* sm, int tid) {
    const u64* in1u = (const u64*)(sm + IN1_OFF);
    const u64* in2u = (const u64*)(sm + IN2_OFF);

    // ---- GEMM1: g1[bt][g] = b1[g] + sum_k in1[k][bt] * WcT1[k][g] ----
    {
        const int s  = tid & 255;   // gate pair: gates 2s, 2s+1
        const int bs = tid >> 8;    // 0/1 -> pairs bs*8 .. bs*8+7
        u64 acc0[8], acc1[8];
        {
            float bb0 = d_b1[2 * s], bb1 = d_b1[2 * s + 1];
            u64 p0 = pack2(bb0, bb0), p1 = pack2(bb1, bb1);
#pragma unroll
            for (int j = 0; j < 8; j++) { acc0[j] = p0; acc1[j] = p1; }
        }
        const float2* __restrict__ w = (const float2*)d_WcT1 + s;  // + k*256
        const u64* hrow = in1u + bs * 8;
#pragma unroll 4
        for (int k = 0; k < K1_; k++) {
            float2 wv = w[k * (G1_ / 2)];
            u64 wa = pack2(wv.x, wv.x);
            u64 wb = pack2(wv.y, wv.y);
            const ulonglong2* h = (const ulonglong2*)(hrow + k * IN1_ROWU);
            ulonglong2 h01 = h[0];
            ulonglong2 h23 = h[1];
            ulonglong2 h45 = h[2];
            ulonglong2 h67 = h[3];
            acc0[0] = fma2(wa, h01.x, acc0[0]); acc1[0] = fma2(wb, h01.x, acc1[0]);
            acc0[1] = fma2(wa, h01.y, acc0[1]); acc1[1] = fma2(wb, h01.y, acc1[1]);
            acc0[2] = fma2(wa, h23.x, acc0[2]); acc1[2] = fma2(wb, h23.x, acc1[2]);
            acc0[3] = fma2(wa, h23.y, acc0[3]); acc1[3] = fma2(wb, h23.y, acc1[3]);
            acc0[4] = fma2(wa, h45.x, acc0[4]); acc1[4] = fma2(wb, h45.x, acc1[4]);
            acc0[5] = fma2(wa, h45.y, acc0[5]); acc1[5] = fma2(wb, h45.y, acc1[5]);
            acc0[6] = fma2(wa, h67.x, acc0[6]); acc1[6] = fma2(wb, h67.x, acc1[6]);
            acc0[7] = fma2(wa, h67.y, acc0[7]); acc1[7] = fma2(wb, h67.y, acc1[7]);
        }
#pragma unroll
        for (int j = 0; j < 8; j++) {
            int p = bs * 8 + j;
            float a0, a1, c0, c1;
            unpack2(acc0[j], a0, a1);   // gate 2s   : bt 2p, 2p+1
            unpack2(acc1[j], c0, c1);   // gate 2s+1 : bt 2p, 2p+1
            *(float2*)(sm + G1S_OFF + (2 * p) * G1S_ROW + 2 * s)     = make_float2(a0, c0);
            *(float2*)(sm + G1S_OFF + (2 * p + 1) * G1S_ROW + 2 * s) = make_float2(a1, c1);
        }
    }
    __syncthreads();

    // ---- pointwise LSTM1 -> h1 into in1 rows 16.., c1 ----
    {
        const int uu = tid & 127;
        const int q  = tid >> 7;     // 0..3 -> bt = 8q..8q+7
#pragma unroll
        for (int j2 = 0; j2 < 4; j2++) {
            float hp[2];
#pragma unroll
            for (int half = 0; half < 2; half++) {
                int bt = 8 * q + 2 * j2 + half;
                const float* row = sm + G1S_OFF + bt * G1S_ROW;
                float gi = row[uu], gf = row[H1_ + uu], gg = row[2 * H1_ + uu], go = row[3 * H1_ + uu];
                float c  = sm[C1_OFF + uu * 33 + bt];
                float cn = sigmoidf_(gf) * c + sigmoidf_(gi) * tanhf_(gg);
                float hn = sigmoidf_(go) * tanhf_(cn);
                sm[C1_OFF + uu * 33 + bt] = cn;
                hp[half] = hn;
            }
            *(float2*)(sm + IN1_OFF + (NF_ + uu) * IN1_ROW + 2 * (4 * q + j2)) = make_float2(hp[0], hp[1]);
        }
    }
    __syncthreads();

    // ---- GEMM2: g2[bt][g] = b2[g] + sum h1*Wih2 + sum h2*Whh2 ----
    {
        const int s2  = tid & 127;   // gates 2s2, 2s2+1
        const int bs2 = tid >> 7;    // 0..3 -> pairs bs2*4 .. +3
        u64 acc0[4], acc1[4];
        {
            float bb0 = d_b2[2 * s2], bb1 = d_b2[2 * s2 + 1];
            u64 p0 = pack2(bb0, bb0), p1 = pack2(bb1, bb1);
#pragma unroll
            for (int j = 0; j < 4; j++) { acc0[j] = p0; acc1[j] = p1; }
        }
        const float2* __restrict__ w = (const float2*)d_WcT2 + s2;  // + k*128
        const u64* h1row = in1u + NF_ * IN1_ROWU + bs2 * 4;
#pragma unroll 4
        for (int k = 0; k < H1_; k++) {
            float2 wv = w[k * (G2_ / 2)];
            u64 wa = pack2(wv.x, wv.x);
            u64 wb = pack2(wv.y, wv.y);
            const ulonglong2* h = (const ulonglong2*)(h1row + k * IN1_ROWU);
            ulonglong2 h01 = h[0];
            ulonglong2 h23 = h[1];
            acc0[0] = fma2(wa, h01.x, acc0[0]); acc1[0] = fma2(wb, h01.x, acc1[0]);
            acc0[1] = fma2(wa, h01.y, acc0[1]); acc1[1] = fma2(wb, h01.y, acc1[1]);
            acc0[2] = fma2(wa, h23.x, acc0[2]); acc1[2] = fma2(wb, h23.x, acc1[2]);
            acc0[3] = fma2(wa, h23.y, acc0[3]); acc1[3] = fma2(wb, h23.y, acc1[3]);
        }
        const u64* h2row = in2u + bs2 * 4;
#pragma unroll 4
        for (int k = 0; k < H2_; k++) {
            float2 wv = w[(H1_ + k) * (G2_ / 2)];
            u64 wa = pack2(wv.x, wv.x);
            u64 wb = pack2(wv.y, wv.y);
            const ulonglong2* h = (const ulonglong2*)(h2row + k * IN1_ROWU);
            ulonglong2 h01 = h[0];
            ulonglong2 h23 = h[1];
            acc0[0] = fma2(wa, h01.x, acc0[0]); acc1[0] = fma2(wb, h01.x, acc1[0]);
            acc0[1] = fma2(wa, h01.y, acc0[1]); acc1[1] = fma2(wb, h01.y, acc1[1]);
            acc0[2] = fma2(wa, h23.x, acc0[2]); acc1[2] = fma2(wb, h23.x, acc1[2]);
            acc0[3] = fma2(wa, h23.y, acc0[3]); acc1[3] = fma2(wb, h23.y, acc1[3]);
        }
#pragma unroll
        for (int j = 0; j < 4; j++) {
            int p = bs2 * 4 + j;
            float a0, a1, c0, c1;
            unpack2(acc0[j], a0, a1);
            unpack2(acc1[j], c0, c1);
            *(float2*)(sm + G2S_OFF + (2 * p) * G2S_ROW + 2 * s2)     = make_float2(a0, c0);
            *(float2*)(sm + G2S_OFF + (2 * p + 1) * G2S_ROW + 2 * s2) = make_float2(a1, c1);
        }
    }
    __syncthreads();

    // ---- pointwise LSTM2 -> h2 into in2, c2 ----
    {
        const int uu = tid & 63;
        const int q  = tid >> 6;     // 0..7 -> bt = 4q..4q+3
#pragma unroll
        for (int j = 0; j < 2; j++) {
            float hp[2];
#pragma unroll
            for (int half = 0; half < 2; half++) {
                int bt = 4 * q + 2 * j + half;
                const float* row = sm + G2S_OFF + bt * G2S_ROW;
                float gi = row[uu], gf = row[H2_ + uu], gg = row[2 * H2_ + uu], go = row[3 * H2_ + uu];
                float c  = sm[C2_OFF + uu * 33 + bt];
                float cn = sigmoidf_(gf) * c + sigmoidf_(gi) * tanhf_(gg);
                float hn = sigmoidf_(go) * tanhf_(cn);
                sm[C2_OFF + uu * 33 + bt] = cn;
                hp[half] = hn;
            }
            *(float2*)(sm + IN2_OFF + uu * IN1_ROW + 2 * (2 * q + j)) = make_float2(hp[0], hp[1]);
        }
    }
    __syncthreads();
}

// ---------------- weight prep: transpose + bias fuse ----------------
__global__ void prep_kernel(const float* __restrict__ Wih1, const float* __restrict__ Whh1,
                            const float* __restrict__ bih1, const float* __restrict__ bhh1,
                            const float* __restrict__ Wih2, const float* __restrict__ Whh2,
                            const float* __restrict__ bih2, const float* __restrict__ bhh2) {
    int idx = blockIdx.x * blockDim.x + threadIdx.x;
    int stride = gridDim.x * blockDim.x;
    for (int i = idx; i < K1_ * G1_; i += stride) {
        int k = i / G1_, g = i % G1_;
        d_WcT1[i] = (k < NF_) ? Wih1[g * NF_ + k] : Whh1[g * H1_ + (k - NF_)];
    }
    for (int i = idx; i < K2_ * G2_; i += stride) {
        int k = i / G2_, g = i % G2_;
        d_WcT2[i] = (k < H1_) ? Wih2[g * H1_ + k] : Whh2[g * H2_ + (k - H1_)];
    }
    if (idx < G1_) d_b1[idx] = bih1[idx] + bhh1[idx];
    if (idx < G2_) d_b2[idx] = bih2[idx] + bhh2[idx];
}

// ---------------- main persistent kernel ----------------
__global__ void __launch_bounds__(NTHREADS, 1) lstm_main(
    const float* __restrict__ xh, const float* __restrict__ xfut,
    const float* __restrict__ Wd, const float* __restrict__ bd,
    const float* __restrict__ Wf, const float* __restrict__ bf,
    const float* __restrict__ ob, float* __restrict__ out) {
    extern __shared__ float sm[];
    const int tid = threadIdx.x;
    const int b0  = blockIdx.x * BT_;

    // zero all state (h rows, c, buffers)
    for (int i = tid; i < SMEM_FLOATS; i += NTHREADS) sm[i] = 0.0f;
    __syncthreads();

    // ---------- encoder ----------
    for (int t = 0; t < T_; t++) {
        {
            int f = tid >> 5, bt = tid & 31;
            sm[IN1_OFF + f * IN1_ROW + bt] =
                xh[(size_t)(b0 + bt) * T_ * NF_ + t * NF_ + f];
        }
        __syncthreads();
        lstm_step(sm, tid);
    }

    // cur = x_history[:, T-1, NF-NT:]
    if (tid < BT_ * NT_) {
        int bt = tid >> 1, tt = tid & 1;
        sm[IN1_OFF + (NF_ - NT_ + tt) * IN1_ROW + bt] =
            xh[(size_t)(b0 + bt) * T_ * NF_ + (T_ - 1) * NF_ + (NF_ - NT_) + tt];
    }

    // ---------- decoder ----------
    for (int st = 0; st < S_; st++) {
        if (tid < BT_ * (NF_ - NT_)) {             // 448 threads load refs
            int f = tid % (NF_ - NT_), bt = tid / (NF_ - NT_);
            sm[IN1_OFF + f * IN1_ROW + bt] =
                xfut[(size_t)(b0 + bt) * S_ * (NF_ - NT_) + st * (NF_ - NT_) + f];
        }
        __syncthreads();
        lstm_step(sm, tid);

        // dense: d = relu(h2 @ Wd^T + bd), 32x32
        {
            int du = tid & 31, bq = tid >> 5;      // bq 0..15 -> bt = bq, bq+16
            float acc0 = 0.0f, acc1 = 0.0f;
#pragma unroll 4
            for (int k = 0; k < H2_; k++) {
                float wv = Wd[du * H2_ + k];
                acc0 = fmaf(wv, sm[IN2_OFF + k * IN1_ROW + bq], acc0);
                acc1 = fmaf(wv, sm[IN2_OFF + k * IN1_ROW + bq + 16], acc1);
            }
            float bdv = bd[du];
            sm[DS_OFF + bq * 33 + du]        = fmaxf(acc0 + bdv, 0.0f);
            sm[DS_OFF + (bq + 16) * 33 + du] = fmaxf(acc1 + bdv, 0.0f);
        }
        __syncthreads();

        // pred = d @ Wf^T + bf + out_bias; write out + feedback cur
        if (tid < BT_ * NT_) {
            int bt = tid >> 1, tt = tid & 1;
            float acc = 0.0f;
#pragma unroll
            for (int k = 0; k < H3_; k++)
                acc = fmaf(sm[DS_OFF + bt * 33 + k], Wf[tt * H3_ + k], acc);
            float p = acc + bf[tt] + ob[tt];
            out[(size_t)(b0 + bt) * S_ * NT_ + st * NT_ + tt] = p;
            sm[IN1_OFF + (NF_ - NT_ + tt) * IN1_ROW + bt] = p;
        }
        __syncthreads();
    }
}

// ---------------- launch ----------------
extern "C" void kernel_launch(void* const* d_in, const int* in_sizes, int n_in,
                              void* d_out, int out_size) {
    (void)in_sizes; (void)n_in; (void)out_size;
    const float* xh   = (const float*)d_in[0];
    const float* xfut = (const float*)d_in[1];
    const float* Wih1 = (const float*)d_in[2];
    const float* Whh1 = (const float*)d_in[3];
    const float* bih1 = (const float*)d_in[4];
    const float* bhh1 = (const float*)d_in[5];
    const float* Wih2 = (const float*)d_in[6];
    const float* Whh2 = (const float*)d_in[7];
    const float* bih2 = (const float*)d_in[8];
    const float* bhh2 = (const float*)d_in[9];
    const float* Wd   = (const float*)d_in[10];
    const float* bd   = (const float*)d_in[11];
    const float* Wf   = (const float*)d_in[12];
    const float* bf   = (const float*)d_in[13];
    const float* ob   = (const float*)d_in[14];
    float* out = (float*)d_out;

    cudaFuncSetAttribute(lstm_main, cudaFuncAttributeMaxDynamicSharedMemorySize, SMEM_BYTES);
    prep_kernel<<<128, 256>>>(Wih1, Whh1, bih1, bhh1, Wih2, Whh2, bih2, bhh2);
    lstm_main<<<NBLK, NTHREADS, SMEM_BYTES>>>(xh, xfut, Wd, bd, Wf, bf, ob, out);
}